// round 7
// baseline (speedup 1.0000x reference)
#include <cuda_runtime.h>

// Problem geometry: N = (262144, 65536, 16384), final block rank R = 21
#define NI 16384
#define A_ELEMS (21 * 21 * NI)
#define LOGDET_IDX (2 * A_ELEMS)
#define ZOUT_OFF (LOGDET_IDX + 1)   // odd float offset -> scalar stores only
#define ZOUT_PLANE (21 * NI)
#define TILE_I 32
#define NBLK (NI / TILE_I)          // 512
#define NTHREADS 256                // 8 warps

struct Cpx { float re, im; };

__device__ __forceinline__ Cpx cmul(Cpx a, Cpx b) {
    Cpx r; r.re = a.re * b.re - a.im * b.im; r.im = a.re * b.im + a.im * b.re; return r;
}
// a * conj(b)
__device__ __forceinline__ Cpx cmulc(Cpx a, Cpx b) {
    Cpx r; r.re = a.re * b.re + a.im * b.im; r.im = a.im * b.re - a.re * b.im; return r;
}
__device__ __forceinline__ Cpx cinv(Cpx a) {
    float d = 1.0f / (a.re * a.re + a.im * a.im);
    Cpx r; r.re = a.re * d; r.im = -a.im * d; return r;
}

__device__ double g_ld[NBLK];
__device__ unsigned int g_count = 0;

__global__ void __launch_bounds__(NTHREADS, 5) kmain(
    const float* __restrict__ l00r, const float* __restrict__ l00i,
    const float* __restrict__ l01r, const float* __restrict__ l01i,
    const float* __restrict__ l02r, const float* __restrict__ l02i,
    const float* __restrict__ l11r, const float* __restrict__ l11i,
    const float* __restrict__ l12r, const float* __restrict__ l12i,
    const float* __restrict__ l22r, const float* __restrict__ l22i,
    const float* __restrict__ zre,  const float* __restrict__ zim,
    float* __restrict__ out)
{
    __shared__ float2 shT2[20 * 32];      // level-2 T
    __shared__ float2 shA1[100 * 32];     // 4 x (5x5) level-1 inverse
    __shared__ float2 shZ[21 * 32];       // z {re,im}
    __shared__ float2 shM2[4 * 32];
    __shared__ float2 shInvS2[32];
    __shared__ double shLd[5];
    __shared__ int shLast;

    const int lane = threadIdx.x & 31;
    const int warp = threadIdx.x >> 5;
    const int base = blockIdx.x * TILE_I;
    const int i = base + lane;

    double acc = 0.0;

    // warp 4 prefetches l22 early (hides latency behind phase 1)
    float pre22r = 0.f, pre22i = 0.f;
    if (warp == 4) { pre22r = l22r[i]; pre22i = l22i[i]; }

    // ---- Phase 1: warps 0..3, s = warp ----
    if (warp < 4) {
        const int s = warp;
        const int m = s * NI + i;

        Cpx a0[4], T1[4];
        Cpx M1; M1.re = 0.f; M1.im = 0.f;
        #pragma unroll
        for (int jj = 0; jj < 4; jj++) {
            const int idx = (jj * 4 + s) * NI + i;
            Cpx l00; l00.re = l00r[idx]; l00.im = l00i[idx];
            Cpx l01; l01.re = l01r[idx]; l01.im = l01i[idx];
            a0[jj] = cinv(l00);
            T1[jj] = cmul(l01, a0[jj]);
            Cpx t = cmulc(T1[jj], l01);
            M1.re += t.re; M1.im += t.im;
            acc += 0.5 * (double)logf(l00.re * l00.re + l00.im * l00.im);
        }
        Cpx S1; S1.re = l11r[m] - M1.re; S1.im = l11i[m] - M1.im;
        acc += 0.5 * (double)logf(S1.re * S1.re + S1.im * S1.im);
        const Cpx invS1 = cinv(S1);

        Cpx b[5];
        #pragma unroll
        for (int p = 0; p < 4; p++) {
            const int idx = (p * 4 + s) * NI + i;
            b[p].re = l02r[idx]; b[p].im = l02i[idx];
        }
        b[4].re = l12r[m]; b[4].im = l12i[m];

        Cpx w; w.re = 0.f; w.im = 0.f;
        #pragma unroll
        for (int p = 0; p < 4; p++) {
            Cpx t = cmulc(b[p], T1[p]);
            w.re += t.re; w.im += t.im;
        }
        Cpx wm; wm.re = w.re - b[4].re; wm.im = w.im - b[4].im;

        Cpx t2b = cmul(invS1, b[4]);
        Cpx M2; M2.re = 0.f; M2.im = 0.f;
        Cpx P1[4];
        #pragma unroll
        for (int q = 0; q < 4; q++) {
            P1[q] = cmul(T1[q], invS1);
            Cpx t2 = cmul(P1[q], wm);
            Cpx t = cmul(a0[q], b[q]);
            t2.re += t.re; t2.im += t.im;
            shT2[(q * 4 + s) * 32 + lane] = make_float2(t2.re, t2.im);
            Cpx mm = cmulc(t2, b[q]);
            M2.re += mm.re; M2.im += mm.im;
            Cpx u = cmulc(b[q], P1[q]);
            t2b.re -= u.re; t2b.im -= u.im;
        }
        shT2[(16 + s) * 32 + lane] = make_float2(t2b.re, t2b.im);
        Cpx mm = cmulc(t2b, b[4]);
        M2.re += mm.re; M2.im += mm.im;
        shM2[s * 32 + lane] = make_float2(M2.re, M2.im);

        // A1 (5x5) for this s
        #pragma unroll
        for (int p = 0; p < 4; p++) {
            #pragma unroll
            for (int q = 0; q < 4; q++) {
                Cpx v = cmulc(P1[p], T1[q]);
                if (q == p) { v.re += a0[p].re; v.im += a0[p].im; }
                shA1[(s * 25 + p * 5 + q) * 32 + lane] = make_float2(v.re, v.im);
            }
            shA1[(s * 25 + p * 5 + 4) * 32 + lane] = make_float2(-P1[p].re, -P1[p].im);
        }
        #pragma unroll
        for (int q = 0; q < 4; q++)
            shA1[(s * 25 + 20 + q) * 32 + lane] = make_float2(-P1[q].re, P1[q].im);
        shA1[(s * 25 + 24) * 32 + lane] = make_float2(invS1.re, invS1.im);
    }

    // ---- z staging: warp w loads planes w, w+8, (w+16 if w<5) ----
    shZ[warp * 32 + lane] = make_float2(zre[warp * NI + i], zim[warp * NI + i]);
    shZ[(warp + 8) * 32 + lane] = make_float2(zre[(warp + 8) * NI + i], zim[(warp + 8) * NI + i]);
    if (warp < 5)
        shZ[(warp + 16) * 32 + lane] = make_float2(zre[(warp + 16) * NI + i], zim[(warp + 16) * NI + i]);

    __syncthreads();

    // ---- Phase 1b: warp 4 computes S2 / invS2 / log|S2| ----
    if (warp == 4) {
        float2 m0 = shM2[0 * 32 + lane], m1 = shM2[1 * 32 + lane],
               m2 = shM2[2 * 32 + lane], m3 = shM2[3 * 32 + lane];
        Cpx S2; S2.re = pre22r - (m0.x + m1.x + m2.x + m3.x);
                S2.im = pre22i - (m0.y + m1.y + m2.y + m3.y);
        acc = 0.5 * (double)logf(S2.re * S2.re + S2.im * S2.im);
        Cpx inv = cinv(S2);
        shInvS2[lane] = make_float2(inv.re, inv.im);
    }
    if (warp < 5) {
        #pragma unroll
        for (int off = 16; off > 0; off >>= 1)
            acc += __shfl_down_sync(0xffffffffu, acc, off);
        if (lane == 0) shLd[warp] = acc;
    }
    __syncthreads();

    // ---- Phase 2: warp w owns rows w, w+8, (w+16 if w<5); all share s = w&3 ----
    float2 vi = shInvS2[lane];
    Cpx invS2; invS2.re = vi.x; invS2.im = vi.y;

    const int s = warp & 3;
    const int j0 = warp, j1 = warp + 8, j2 = warp + 16;
    const int p0 = warp >> 2;            // 0 or 1
    const int p1 = (warp + 8) >> 2;      // 2 or 3
    const bool hasR2 = (warp < 5);
    const bool border = (warp == 4);     // row 20

    float2 t0 = shT2[j0 * 32 + lane];
    float2 t1 = shT2[j1 * 32 + lane];
    Cpx T2j0; T2j0.re = t0.x; T2j0.im = t0.y;
    Cpx T2j1; T2j1.re = t1.x; T2j1.im = t1.y;
    Cpx P2_0 = cmul(T2j0, invS2);
    Cpx P2_1 = cmul(T2j1, invS2);
    Cpx P2_2; P2_2.re = 0.f; P2_2.im = 0.f;
    if (hasR2 && !border) {
        float2 t2v = shT2[j2 * 32 + lane];
        Cpx T2j2; T2j2.re = t2v.x; T2j2.im = t2v.y;
        P2_2 = cmul(T2j2, invS2);
    }

    Cpx za0, za1, za2;
    za0.re = za0.im = za1.re = za1.im = za2.re = za2.im = 0.f;

    float* oR0 = out + (size_t)(j0 * 21) * NI + i;
    float* oI0 = out + A_ELEMS + (size_t)(j0 * 21) * NI + i;
    float* oR1 = out + (size_t)(j1 * 21) * NI + i;
    float* oI1 = out + A_ELEMS + (size_t)(j1 * 21) * NI + i;
    float* oR2 = out + (size_t)(j2 * 21) * NI + i;
    float* oI2 = out + A_ELEMS + (size_t)(j2 * 21) * NI + i;

    #pragma unroll
    for (int k = 0; k < 20; k++) {
        float2 tkv = shT2[k * 32 + lane];
        Cpx Tk; Tk.re = tkv.x; Tk.im = tkv.y;
        float2 zkv = shZ[k * 32 + lane];
        Cpx zk; zk.re = zkv.x; zk.im = zkv.y;
        const bool hit = ((k & 3) == s);
        const int q = k >> 2;

        // row 0
        {
            Cpx v = cmulc(P2_0, Tk);
            if (hit) {
                float2 a = shA1[(s * 25 + p0 * 5 + q) * 32 + lane];
                v.re += a.x; v.im += a.y;
            }
            oR0[(size_t)k * NI] = v.re; oI0[(size_t)k * NI] = v.im;
            Cpx t = cmul(zk, v); za0.re += t.re; za0.im += t.im;
        }
        // row 1
        {
            Cpx v = cmulc(P2_1, Tk);
            if (hit) {
                float2 a = shA1[(s * 25 + p1 * 5 + q) * 32 + lane];
                v.re += a.x; v.im += a.y;
            }
            oR1[(size_t)k * NI] = v.re; oI1[(size_t)k * NI] = v.im;
            Cpx t = cmul(zk, v); za1.re += t.re; za1.im += t.im;
        }
        // row 2
        if (hasR2) {
            Cpx v;
            if (border) {
                Cpx P2k = cmul(Tk, invS2);
                v.re = -P2k.re; v.im = P2k.im;        // -conj(P2[k])
            } else {
                v = cmulc(P2_2, Tk);
                if (hit) {
                    float2 a = shA1[(s * 25 + 4 * 5 + q) * 32 + lane];
                    v.re += a.x; v.im += a.y;
                }
            }
            oR2[(size_t)k * NI] = v.re; oI2[(size_t)k * NI] = v.im;
            Cpx t = cmul(zk, v); za2.re += t.re; za2.im += t.im;
        }
    }
    // column k = 20
    {
        float2 zkv = shZ[20 * 32 + lane];
        Cpx zk; zk.re = zkv.x; zk.im = zkv.y;
        Cpx v0; v0.re = -P2_0.re; v0.im = -P2_0.im;
        oR0[(size_t)20 * NI] = v0.re; oI0[(size_t)20 * NI] = v0.im;
        Cpx t = cmul(zk, v0); za0.re += t.re; za0.im += t.im;

        Cpx v1; v1.re = -P2_1.re; v1.im = -P2_1.im;
        oR1[(size_t)20 * NI] = v1.re; oI1[(size_t)20 * NI] = v1.im;
        t = cmul(zk, v1); za1.re += t.re; za1.im += t.im;

        if (hasR2) {
            Cpx v2;
            if (border) { v2 = invS2; }
            else { v2.re = -P2_2.re; v2.im = -P2_2.im; }
            oR2[(size_t)20 * NI] = v2.re; oI2[(size_t)20 * NI] = v2.im;
            t = cmul(zk, v2); za2.re += t.re; za2.im += t.im;
        }
    }

    // zout (ZOUT_OFF is odd -> scalar stores)
    out[ZOUT_OFF + (size_t)j0 * NI + i] = za0.re;
    out[ZOUT_OFF + ZOUT_PLANE + (size_t)j0 * NI + i] = za0.im;
    out[ZOUT_OFF + (size_t)j1 * NI + i] = za1.re;
    out[ZOUT_OFF + ZOUT_PLANE + (size_t)j1 * NI + i] = za1.im;
    if (hasR2) {
        out[ZOUT_OFF + (size_t)j2 * NI + i] = za2.re;
        out[ZOUT_OFF + ZOUT_PLANE + (size_t)j2 * NI + i] = za2.im;
    }

    // ---- logdet: per-block partial, last block finalizes ----
    if (threadIdx.x == 0) {
        double p = shLd[0] + shLd[1] + shLd[2] + shLd[3] + shLd[4];
        g_ld[blockIdx.x] = p;
        __threadfence();
        unsigned int v = atomicAdd(&g_count, 1u);
        shLast = (v == NBLK - 1) ? 1 : 0;
    }
    __syncthreads();
    if (shLast && warp == 0) {
        double a = 0.0;
        #pragma unroll
        for (int q = 0; q < NBLK / 32; q++)
            a += g_ld[q * 32 + lane];
        #pragma unroll
        for (int off = 16; off > 0; off >>= 1)
            a += __shfl_xor_sync(0xffffffffu, a, off);
        if (lane == 0) {
            out[LOGDET_IDX] = (float)a;
            g_count = 0;   // reset for graph replay
        }
    }
}

extern "C" void kernel_launch(void* const* d_in, const int* in_sizes, int n_in,
                              void* d_out, int out_size)
{
    const float* l00r = (const float*)d_in[0];
    const float* l00i = (const float*)d_in[1];
    const float* l01r = (const float*)d_in[2];
    const float* l01i = (const float*)d_in[3];
    const float* l02r = (const float*)d_in[4];
    const float* l02i = (const float*)d_in[5];
    const float* l11r = (const float*)d_in[6];
    const float* l11i = (const float*)d_in[7];
    const float* l12r = (const float*)d_in[8];
    const float* l12i = (const float*)d_in[9];
    const float* l22r = (const float*)d_in[10];
    const float* l22i = (const float*)d_in[11];
    const float* zre  = (const float*)d_in[12];
    const float* zim  = (const float*)d_in[13];
    float* out = (float*)d_out;

    kmain<<<NBLK, NTHREADS>>>(l00r, l00i, l01r, l01i, l02r, l02i,
                              l11r, l11i, l12r, l12i, l22r, l22i,
                              zre, zim, out);
}

// round 8
// speedup vs baseline: 1.0861x; 1.0861x over previous
#include <cuda_runtime.h>

// Problem geometry: N = (262144, 65536, 16384), final block rank R = 21
#define NI 16384
#define A_ELEMS (21 * 21 * NI)
#define LOGDET_IDX (2 * A_ELEMS)
#define ZOUT_OFF (LOGDET_IDX + 1)   // odd float offset -> scalar stores only
#define ZOUT_PLANE (21 * NI)
#define TILE_I 32
#define NBLK (NI / TILE_I)          // 512
#define NTHREADS 224                // 7 warps, 3 rows each

struct Cpx { float re, im; };

__device__ __forceinline__ Cpx cmul(Cpx a, Cpx b) {
    Cpx r; r.re = a.re * b.re - a.im * b.im; r.im = a.re * b.im + a.im * b.re; return r;
}
// a * conj(b)
__device__ __forceinline__ Cpx cmulc(Cpx a, Cpx b) {
    Cpx r; r.re = a.re * b.re + a.im * b.im; r.im = a.im * b.re - a.re * b.im; return r;
}
__device__ __forceinline__ Cpx cinv(Cpx a) {
    float d = 1.0f / (a.re * a.re + a.im * a.im);
    Cpx r; r.re = a.re * d; r.im = -a.im * d; return r;
}

__device__ double g_ld[NBLK];
__device__ unsigned int g_count = 0;

__global__ void __launch_bounds__(NTHREADS, 5) kmain(
    const float* __restrict__ l00r, const float* __restrict__ l00i,
    const float* __restrict__ l01r, const float* __restrict__ l01i,
    const float* __restrict__ l02r, const float* __restrict__ l02i,
    const float* __restrict__ l11r, const float* __restrict__ l11i,
    const float* __restrict__ l12r, const float* __restrict__ l12i,
    const float* __restrict__ l22r, const float* __restrict__ l22i,
    const float* __restrict__ zre,  const float* __restrict__ zim,
    float* __restrict__ out)
{
    __shared__ float4 shTZ[21 * 32];        // .xy = T2[k], .zw = z[k]
    __shared__ float2 shL1[4 * 13 * 32];    // per s: P1[0..3], T1[0..3], a0[0..3], invS1
    __shared__ float2 shM2[4 * 32];
    __shared__ float2 shInvS2[32];
    __shared__ float  shLd[5];
    __shared__ int    shLast;

    const int lane = threadIdx.x & 31;
    const int warp = threadIdx.x >> 5;
    const int i = blockIdx.x * TILE_I + lane;

    float facc = 0.f;
    float pre22r = 0.f, pre22i = 0.f;

    if (warp < 4) {
        // ---- Phase 1: s = warp ----
        const int s = warp;
        const int m = s * NI + i;

        Cpx a0[4], T1[4];
        Cpx M1; M1.re = 0.f; M1.im = 0.f;
        #pragma unroll
        for (int jj = 0; jj < 4; jj++) {
            const int idx = (jj * 4 + s) * NI + i;
            Cpx l00; l00.re = l00r[idx]; l00.im = l00i[idx];
            Cpx l01; l01.re = l01r[idx]; l01.im = l01i[idx];
            a0[jj] = cinv(l00);
            T1[jj] = cmul(l01, a0[jj]);
            Cpx t = cmulc(T1[jj], l01);
            M1.re += t.re; M1.im += t.im;
            facc += 0.5f * __logf(l00.re * l00.re + l00.im * l00.im);
        }
        Cpx S1; S1.re = l11r[m] - M1.re; S1.im = l11i[m] - M1.im;
        facc += 0.5f * __logf(S1.re * S1.re + S1.im * S1.im);
        const Cpx invS1 = cinv(S1);

        Cpx b[5];
        #pragma unroll
        for (int p = 0; p < 4; p++) {
            const int idx = (p * 4 + s) * NI + i;
            b[p].re = l02r[idx]; b[p].im = l02i[idx];
        }
        b[4].re = l12r[m]; b[4].im = l12i[m];

        Cpx w; w.re = 0.f; w.im = 0.f;
        #pragma unroll
        for (int p = 0; p < 4; p++) {
            Cpx t = cmulc(b[p], T1[p]);
            w.re += t.re; w.im += t.im;
        }
        Cpx wm; wm.re = w.re - b[4].re; wm.im = w.im - b[4].im;

        Cpx t2b = cmul(invS1, b[4]);
        Cpx M2; M2.re = 0.f; M2.im = 0.f;
        Cpx P1[4];
        #pragma unroll
        for (int q = 0; q < 4; q++) {
            P1[q] = cmul(T1[q], invS1);
            Cpx t2 = cmul(P1[q], wm);
            Cpx t = cmul(a0[q], b[q]);
            t2.re += t.re; t2.im += t.im;
            *(float2*)&shTZ[(q * 4 + s) * 32 + lane] = make_float2(t2.re, t2.im);
            Cpx mm = cmulc(t2, b[q]);
            M2.re += mm.re; M2.im += mm.im;
            Cpx u = cmulc(b[q], P1[q]);
            t2b.re -= u.re; t2b.im -= u.im;
        }
        *(float2*)&shTZ[(16 + s) * 32 + lane] = make_float2(t2b.re, t2b.im);
        Cpx mm = cmulc(t2b, b[4]);
        M2.re += mm.re; M2.im += mm.im;
        shM2[s * 32 + lane] = make_float2(M2.re, M2.im);

        // compact level-1 state
        #pragma unroll
        for (int q = 0; q < 4; q++) {
            shL1[(s * 13 + q) * 32 + lane]     = make_float2(P1[q].re, P1[q].im);
            shL1[(s * 13 + 4 + q) * 32 + lane] = make_float2(T1[q].re, T1[q].im);
            shL1[(s * 13 + 8 + q) * 32 + lane] = make_float2(a0[q].re, a0[q].im);
        }
        shL1[(s * 13 + 12) * 32 + lane] = make_float2(invS1.re, invS1.im);
    } else {
        // ---- z staging: warps 4..6 load 7 planes each into shTZ .zw ----
        if (warp == 4) { pre22r = l22r[i]; pre22i = l22i[i]; }
        const int pbase = (warp - 4) * 7;
        #pragma unroll
        for (int t = 0; t < 7; t++) {
            const int pl = pbase + t;
            float zr = zre[pl * NI + i];
            float zi = zim[pl * NI + i];
            *(((float2*)&shTZ[pl * 32 + lane]) + 1) = make_float2(zr, zi);
        }
    }
    __syncthreads();

    // ---- Phase 1b: warp 4 computes S2 / invS2 / log|S2| ----
    if (warp == 4) {
        float2 m0 = shM2[0 * 32 + lane], m1 = shM2[1 * 32 + lane],
               m2 = shM2[2 * 32 + lane], m3 = shM2[3 * 32 + lane];
        Cpx S2; S2.re = pre22r - (m0.x + m1.x + m2.x + m3.x);
                S2.im = pre22i - (m0.y + m1.y + m2.y + m3.y);
        facc = 0.5f * __logf(S2.re * S2.re + S2.im * S2.im);
        Cpx inv = cinv(S2);
        shInvS2[lane] = make_float2(inv.re, inv.im);
    }
    if (warp < 5) {
        #pragma unroll
        for (int off = 16; off > 0; off >>= 1)
            facc += __shfl_down_sync(0xffffffffu, facc, off);
        if (lane == 0) shLd[warp] = facc;
    }
    __syncthreads();

    // ---- Phase 2: warp w owns rows w, w+7, w+14 ----
    float2 iv = shInvS2[lane];
    Cpx invS2; invS2.re = iv.x; invS2.im = iv.y;

    Cpx P2[3], P1p[3], a0p[3], iS1[3], za[3];
    int sr[3], pr[3];
    bool isB2[3];
    float *oR[3], *oI[3];

    #pragma unroll
    for (int r = 0; r < 3; r++) {
        const int j = warp + 7 * r;
        sr[r] = j & 3; pr[r] = j >> 2; isB2[r] = (j == 20);
        oR[r] = out + (size_t)(j * 21) * NI + i;
        oI[r] = out + A_ELEMS + (size_t)(j * 21) * NI + i;
        za[r].re = 0.f; za[r].im = 0.f;
        P2[r].re = P2[r].im = 0.f;
        P1p[r].re = P1p[r].im = 0.f;
        a0p[r].re = a0p[r].im = 0.f;
        iS1[r].re = iS1[r].im = 0.f;
        if (!isB2[r]) {
            float2 t = *(const float2*)&shTZ[j * 32 + lane];
            Cpx T2j; T2j.re = t.x; T2j.im = t.y;
            P2[r] = cmul(T2j, invS2);
            if (pr[r] == 4) {
                float2 v = shL1[(sr[r] * 13 + 12) * 32 + lane];
                iS1[r].re = v.x; iS1[r].im = v.y;
            } else {
                float2 a = shL1[(sr[r] * 13 + pr[r]) * 32 + lane];
                P1p[r].re = a.x; P1p[r].im = a.y;
                float2 c = shL1[(sr[r] * 13 + 8 + pr[r]) * 32 + lane];
                a0p[r].re = c.x; a0p[r].im = c.y;
            }
        }
    }

    #pragma unroll
    for (int k = 0; k < 20; k++) {
        float4 tz = shTZ[k * 32 + lane];
        Cpx Tk; Tk.re = tz.x; Tk.im = tz.y;
        Cpx zk; zk.re = tz.z; zk.im = tz.w;
        #pragma unroll
        for (int r = 0; r < 3; r++) {
            Cpx v;
            if (isB2[r]) {
                Cpx P = cmul(Tk, invS2);
                v.re = -P.re; v.im = P.im;                 // -conj(P2[k])
            } else {
                v = cmulc(P2[r], Tk);
                if ((k & 3) == sr[r]) {                    // warp-uniform A1 hit
                    const int q = k >> 2;
                    if (pr[r] == 4) {
                        if (q == 4) { v.re += iS1[r].re; v.im += iS1[r].im; }
                        else {
                            float2 p1q = shL1[(sr[r] * 13 + q) * 32 + lane];
                            v.re -= p1q.x; v.im += p1q.y;  // -conj(P1[q])
                        }
                    } else {
                        if (q == 4) { v.re -= P1p[r].re; v.im -= P1p[r].im; }
                        else {
                            float2 t1 = shL1[(sr[r] * 13 + 4 + q) * 32 + lane];
                            Cpx T1q; T1q.re = t1.x; T1q.im = t1.y;
                            Cpx tt = cmulc(P1p[r], T1q);
                            v.re += tt.re; v.im += tt.im;
                            if (q == pr[r]) { v.re += a0p[r].re; v.im += a0p[r].im; }
                        }
                    }
                }
            }
            oR[r][(size_t)k * NI] = v.re;
            oI[r][(size_t)k * NI] = v.im;
            Cpx t = cmul(zk, v);
            za[r].re += t.re; za[r].im += t.im;
        }
    }
    // column k = 20
    {
        float4 tz = shTZ[20 * 32 + lane];
        Cpx zk; zk.re = tz.z; zk.im = tz.w;
        #pragma unroll
        for (int r = 0; r < 3; r++) {
            Cpx v;
            if (isB2[r]) v = invS2;
            else { v.re = -P2[r].re; v.im = -P2[r].im; }
            oR[r][(size_t)20 * NI] = v.re;
            oI[r][(size_t)20 * NI] = v.im;
            Cpx t = cmul(zk, v);
            za[r].re += t.re; za[r].im += t.im;
        }
    }
    // zout (ZOUT_OFF odd -> scalar stores)
    #pragma unroll
    for (int r = 0; r < 3; r++) {
        const int j = warp + 7 * r;
        out[ZOUT_OFF + (size_t)j * NI + i] = za[r].re;
        out[ZOUT_OFF + ZOUT_PLANE + (size_t)j * NI + i] = za[r].im;
    }

    // ---- logdet: per-block partial, last block finalizes ----
    if (threadIdx.x == 0) {
        double p = (double)(shLd[0] + shLd[1] + shLd[2] + shLd[3] + shLd[4]);
        g_ld[blockIdx.x] = p;
        __threadfence();
        unsigned int v = atomicAdd(&g_count, 1u);
        shLast = (v == NBLK - 1) ? 1 : 0;
    }
    __syncthreads();
    if (shLast && warp == 0) {
        __threadfence();
        double a = 0.0;
        #pragma unroll
        for (int q = 0; q < NBLK / 32; q++)
            a += g_ld[q * 32 + lane];
        #pragma unroll
        for (int off = 16; off > 0; off >>= 1)
            a += __shfl_xor_sync(0xffffffffu, a, off);
        if (lane == 0) {
            out[LOGDET_IDX] = (float)a;
            g_count = 0;   // reset for graph replay
        }
    }
}

extern "C" void kernel_launch(void* const* d_in, const int* in_sizes, int n_in,
                              void* d_out, int out_size)
{
    const float* l00r = (const float*)d_in[0];
    const float* l00i = (const float*)d_in[1];
    const float* l01r = (const float*)d_in[2];
    const float* l01i = (const float*)d_in[3];
    const float* l02r = (const float*)d_in[4];
    const float* l02i = (const float*)d_in[5];
    const float* l11r = (const float*)d_in[6];
    const float* l11i = (const float*)d_in[7];
    const float* l12r = (const float*)d_in[8];
    const float* l12i = (const float*)d_in[9];
    const float* l22r = (const float*)d_in[10];
    const float* l22i = (const float*)d_in[11];
    const float* zre  = (const float*)d_in[12];
    const float* zim  = (const float*)d_in[13];
    float* out = (float*)d_out;

    kmain<<<NBLK, NTHREADS>>>(l00r, l00i, l01r, l01i, l02r, l02i,
                              l11r, l11i, l12r, l12i, l22r, l22i,
                              zre, zim, out);
}